// round 7
// baseline (speedup 1.0000x reference)
#include <cuda_runtime.h>
#include <cuda_bf16.h>
#include <math.h>
#include <stdint.h>

#define BB   32
#define SS   512
#define INF  512
#define HH   1024
#define NG   4096
#define NCTA 128

// Scratch (static device globals — allocation-free per harness rules)
__device__ float g_gxT[(size_t)SS * NG * BB];   // x-part gates, [s][n][b]
__device__ unsigned g_barCnt;
__device__ unsigned g_barRel;

// Interleaved hi/lo bf16 buffers (K-concatenation trick):
//   A row layout: [hi(0:D) | lo(D:2D) | hi(2D:3D)]  (D = 512 for x, 1024 for h)
//   B row layout: [hi | hi | lo]
// so C = A'·B'^T over K' = 3D equals the 3-term split product.
// g_Abig rows are m = b*512 + s; row stride 3072. Doubles as the recurrent
// h ping buffer: hi plane at col j, lo plane at col 1024+j, hi again 2048+j.
__device__ __nv_bfloat16 g_Abig[(size_t)16384 * 3072];
__device__ __nv_bfloat16 g_B0big[(size_t)4096 * 1536];
__device__ __nv_bfloat16 g_B1big[(size_t)4096 * 3072];

// ---------------------------------------------------------------------------
__global__ void init_kernel() {
    if (threadIdx.x == 0 && blockIdx.x == 0) { g_barCnt = 0u; g_barRel = 0u; }
}

// ---------------------------------------------------------------------------
__global__ void split_x(const float* __restrict__ x) {
    int idx = blockIdx.x * blockDim.x + threadIdx.x;   // 16384*512
    if (idx >= 16384 * 512) return;
    int r = idx >> 9, c = idx & 511;
    float v = x[idx];
    __nv_bfloat16 h = __float2bfloat16(v);
    __nv_bfloat16 l = __float2bfloat16(v - __bfloat162float(h));
    size_t base = (size_t)r * 3072;
    g_Abig[base + c]        = h;
    g_Abig[base + 512 + c]  = l;
    g_Abig[base + 1024 + c] = h;
}

// W x-part split: rows 4096, cols D; dst row = [hi | hi | lo], stride ldd.
__global__ void split_w(const float* __restrict__ W, int ldw, int cols,
                        __nv_bfloat16* __restrict__ dst, int ldd)
{
    int idx = blockIdx.x * blockDim.x + threadIdx.x;
    if (idx >= 4096 * cols) return;
    int r = idx / cols, c = idx - r * cols;
    float v = W[(size_t)r * ldw + c];
    __nv_bfloat16 h = __float2bfloat16(v);
    __nv_bfloat16 l = __float2bfloat16(v - __bfloat162float(h));
    size_t base = (size_t)r * ldd;
    dst[base + c]            = h;
    dst[base + cols + c]     = h;
    dst[base + 2 * cols + c] = l;
}

// ---------------------------------------------------------------------------
__device__ __forceinline__ void mma16816(float* d, const uint32_t* a,
                                         const uint32_t* b)
{
    asm volatile(
        "mma.sync.aligned.m16n8k16.row.col.f32.bf16.bf16.f32 "
        "{%0,%1,%2,%3}, {%4,%5,%6,%7}, {%8,%9}, {%0,%1,%2,%3};\n"
        : "+f"(d[0]), "+f"(d[1]), "+f"(d[2]), "+f"(d[3])
        : "r"(a[0]), "r"(a[1]), "r"(a[2]), "r"(a[3]), "r"(b[0]), "r"(b[1]));
}

__device__ __forceinline__ uint32_t smaddr(const void* p) {
    return (uint32_t)__cvta_generic_to_shared(p);
}
#define CP16(dst, src) \
    asm volatile("cp.async.cg.shared.global [%0], [%1], 16;" :: "r"(dst), "l"(src))
#define CPCOMMIT() asm volatile("cp.async.commit_group;")
#define CPWAIT(n)  asm volatile("cp.async.wait_group %0;" :: "n"(n))

// ---------------------------------------------------------------------------
// Generic bf16 GEMM: C[m][n] = sum_k A[m][k]*B[n][k] + bias[n % handled below],
// scattered to g_gxT. CTA tile 128(M)x64(N), warp tile 32x32, k-chunk 64,
// 2-stage cp.async double buffer, 2 CTAs/SM.
#define GX_SMEM_WORDS (2 * 128 * 36 + 2 * 64 * 36)

__global__ __launch_bounds__(256, 2) void gemm_x_bf16(
    const __nv_bfloat16* __restrict__ A, int lda,
    const __nv_bfloat16* __restrict__ B, int ldb,
    const float* __restrict__ bias, int K)
{
    extern __shared__ uint32_t smg[];
    uint32_t* smA = smg;                 // 2 stages x 128 x 36 words
    uint32_t* smB = smg + 2 * 128 * 36;  // 2 stages x  64 x 36 words

    const int tid  = threadIdx.x;
    const int n0   = blockIdx.x * 64;
    const int m0   = blockIdx.y * 128;
    const int wid  = tid >> 5, lane = tid & 31;
    const int wm   = (wid >> 1) * 32;
    const int wn   = (wid & 1) * 32;
    const int g    = lane >> 2, t = lane & 3;

    float acc[2][4][4];
#pragma unroll
    for (int mt = 0; mt < 2; mt++)
#pragma unroll
        for (int nt = 0; nt < 4; nt++)
#pragma unroll
            for (int i = 0; i < 4; i++) acc[mt][nt][i] = 0.0f;

    const int nch = K / 64;

    // stage loader: k-chunk 64 elems = 32 words = 8 x 16B per row
    auto stage = [&](int st, int k0) {
#pragma unroll
        for (int i = 0; i < 4; i++) {
            int q = i * 256 + tid;       // 0..1023 -> A 128 rows x 8 cps
            int r = q >> 3, c = q & 7;
            CP16(smaddr(&smA[(st * 128 + r) * 36 + c * 4]),
                 A + (size_t)(m0 + r) * lda + k0 + c * 8);
        }
#pragma unroll
        for (int i = 0; i < 2; i++) {
            int q = i * 256 + tid;       // 0..511 -> B 64 rows x 8 cps
            int r = q >> 3, c = q & 7;
            CP16(smaddr(&smB[(st * 64 + r) * 36 + c * 4]),
                 B + (size_t)(n0 + r) * ldb + k0 + c * 8);
        }
        CPCOMMIT();
    };

    stage(0, 0);

    for (int ch = 0; ch < nch; ch++) {
        if (ch + 1 < nch) { stage((ch + 1) & 1, (ch + 1) * 64); CPWAIT(1); }
        else              { CPWAIT(0); }
        __syncthreads();

        const uint32_t* uA = smA + (ch & 1) * 128 * 36;
        const uint32_t* uB = smB + (ch & 1) * 64 * 36;

#pragma unroll
        for (int kk = 0; kk < 4; kk++) {
            const int kb = kk * 8;
            uint32_t ah[2][4];
#pragma unroll
            for (int mt = 0; mt < 2; mt++) {
                int r0 = wm + mt * 16;
                ah[mt][0] = uA[(r0 + g)     * 36 + kb + t];
                ah[mt][1] = uA[(r0 + g + 8) * 36 + kb + t];
                ah[mt][2] = uA[(r0 + g)     * 36 + kb + t + 4];
                ah[mt][3] = uA[(r0 + g + 8) * 36 + kb + t + 4];
            }
#pragma unroll
            for (int nt = 0; nt < 4; nt++) {
                int c0 = wn + nt * 8;
                uint32_t bh[2];
                bh[0] = uB[(c0 + g) * 36 + kb + t];
                bh[1] = uB[(c0 + g) * 36 + kb + t + 4];
#pragma unroll
                for (int mt = 0; mt < 2; mt++)
                    mma16816(acc[mt][nt], ah[mt], bh);
            }
        }
        __syncthreads();
    }

    // epilogue: scatter to g_gxT[s][n][b] + bias
#pragma unroll
    for (int mt = 0; mt < 2; mt++) {
        int m1 = m0 + wm + mt * 16 + g;
        int m2 = m1 + 8;
        int b1 = m1 >> 9, s1 = m1 & 511;
        int b2 = m2 >> 9, s2 = m2 & 511;
#pragma unroll
        for (int nt = 0; nt < 4; nt++) {
            int n = n0 + wn + nt * 8 + 2 * t;
            float2 bv = *(const float2*)&bias[n];
            size_t o1 = ((size_t)s1 * NG + n) * BB + b1;
            size_t o2 = ((size_t)s2 * NG + n) * BB + b2;
            g_gxT[o1]      = acc[mt][nt][0] + bv.x;
            g_gxT[o1 + BB] = acc[mt][nt][1] + bv.y;
            g_gxT[o2]      = acc[mt][nt][2] + bv.x;
            g_gxT[o2 + BB] = acc[mt][nt][3] + bv.y;
        }
    }
}

// ---------------------------------------------------------------------------
// Persistent recurrent kernel, HMMA version (proven in R6). 128 CTAs x 256
// thr, 1 CTA/SM. h hi/lo planes live in g_Abig (cols [0,1024) hi,
// [1024,2048) lo), row = b*512 + t, row stride 3072.
#define LS_W_L   16512
#define LS_HC_H  33024
#define LS_HC_L  37248
#define LS_PART  41472
#define LS_SMEM_BYTES (49920 * 4)

__global__ __launch_bounds__(256, 1) void lstm_layer(
    const float* __restrict__ W, int ldw, int Din,
    float* __restrict__ out, int layer)
{
    extern __shared__ uint32_t smu[];
    uint32_t* Wsh = smu;
    uint32_t* Wsl = smu + LS_W_L;
    uint32_t* Hh  = smu + LS_HC_H;
    uint32_t* Hl  = smu + LS_HC_L;
    float*    part = (float*)(smu + LS_PART);

    const int tid  = threadIdx.x;
    const int cta  = blockIdx.x;
    const int j0   = cta * 8;
    const int wid  = tid >> 5, lane = tid & 31;
    const int g    = lane >> 2, t4 = lane & 3;

    // ---- Load + split recurrent W slice once (32 rows x 1024 k) ----
    for (int i = 0; i < 64; i++) {
        int q  = i * 256 + tid;
        int l  = q >> 9;
        int wk = q & 511;
        int gate = l >> 3, jj = l & 7;
        int n = gate * 1024 + j0 + jj;
        float2 v = *(const float2*)(W + (size_t)n * ldw + Din + wk * 2);
        __nv_bfloat16 hx = __float2bfloat16(v.x);
        __nv_bfloat16 hy = __float2bfloat16(v.y);
        __nv_bfloat16 lx = __float2bfloat16(v.x - __bfloat162float(hx));
        __nv_bfloat16 ly = __float2bfloat16(v.y - __bfloat162float(hy));
        Wsh[l * 516 + wk] = (uint32_t)__bfloat16_as_ushort(hx)
                          | ((uint32_t)__bfloat16_as_ushort(hy) << 16);
        Wsl[l * 516 + wk] = (uint32_t)__bfloat16_as_ushort(lx)
                          | ((uint32_t)__bfloat16_as_ushort(ly) << 16);
    }

    const int ub = tid & 31;
    const int uj = tid >> 5;
    const int ujglob = j0 + uj;

    float c_state = 0.0f;
    float h_last  = 0.0f;
    unsigned round = 0;

    __syncthreads();

    for (int tstep = 0; tstep < SS; tstep++) {
        // ---- grid barrier ----
        round++;
        __syncthreads();
        if (tid == 0) {
            __threadfence();
            unsigned arrived = atomicAdd(&g_barCnt, 1u) + 1u;
            if (arrived == round * NCTA) {
                atomicExch(&g_barRel, round);
            } else {
                volatile unsigned* rel = &g_barRel;
                while (*rel < round) {}
            }
            __threadfence();
        }
        __syncthreads();

        float acc[2][4][4];
#pragma unroll
        for (int mt = 0; mt < 2; mt++)
#pragma unroll
            for (int nt = 0; nt < 4; nt++)
#pragma unroll
                for (int i = 0; i < 4; i++) acc[mt][nt][i] = 0.0f;

        if (tstep > 0) {
            for (int cch = 0; cch < 4; cch++) {
                __syncthreads();
#pragma unroll
                for (int i = 0; i < 4; i++) {
                    int q  = i * 256 + tid;
                    int b  = q >> 5, u4 = q & 31;
                    size_t row = (size_t)(b * 512 + tstep - 1) * 3072;
                    size_t bh_ = row + cch * 256;
                    size_t bl_ = row + 1024 + cch * 256;
                    *(uint4*)&Hh[b * 132 + u4 * 4] =
                        __ldcg((const uint4*)(g_Abig + bh_) + u4);
                    *(uint4*)&Hl[b * 132 + u4 * 4] =
                        __ldcg((const uint4*)(g_Abig + bl_) + u4);
                }
                __syncthreads();

#pragma unroll
                for (int s = 0; s < 2; s++) {
                    int ks = wid * 2 + s;
                    int aw = ks * 8 + t4;
                    int bw = cch * 128 + ks * 8 + t4;
                    uint32_t ah[2][4], al[2][4];
#pragma unroll
                    for (int mt = 0; mt < 2; mt++) {
                        int r = mt * 16 + g;
                        ah[mt][0] = Hh[r * 132 + aw];
                        ah[mt][1] = Hh[(r + 8) * 132 + aw];
                        ah[mt][2] = Hh[r * 132 + aw + 4];
                        ah[mt][3] = Hh[(r + 8) * 132 + aw + 4];
                        al[mt][0] = Hl[r * 132 + aw];
                        al[mt][1] = Hl[(r + 8) * 132 + aw];
                        al[mt][2] = Hl[r * 132 + aw + 4];
                        al[mt][3] = Hl[(r + 8) * 132 + aw + 4];
                    }
#pragma unroll
                    for (int nt = 0; nt < 4; nt++) {
                        int rn = nt * 8 + g;
                        uint32_t bh[2], bl[2];
                        bh[0] = Wsh[rn * 516 + bw];
                        bh[1] = Wsh[rn * 516 + bw + 4];
                        bl[0] = Wsl[rn * 516 + bw];
                        bl[1] = Wsl[rn * 516 + bw + 4];
#pragma unroll
                        for (int mt = 0; mt < 2; mt++) {
                            mma16816(acc[mt][nt], ah[mt], bh);
                            mma16816(acc[mt][nt], ah[mt], bl);
                            mma16816(acc[mt][nt], al[mt], bh);
                        }
                    }
                }
            }
            // store partials (scalar — stride 33 is odd; float2 traps)
#pragma unroll
            for (int mt = 0; mt < 2; mt++) {
                int b = mt * 16 + g;
#pragma unroll
                for (int nt = 0; nt < 4; nt++) {
                    int l = nt * 8 + 2 * t4;
                    part[(wid * 32 + b) * 33 + l]     = acc[mt][nt][0];
                    part[(wid * 32 + b) * 33 + l + 1] = acc[mt][nt][1];
                    part[(wid * 32 + b + 8) * 33 + l]     = acc[mt][nt][2];
                    part[(wid * 32 + b + 8) * 33 + l + 1] = acc[mt][nt][3];
                }
            }
            __syncthreads();
        }

        // ---- reduce + activations + state update ----
        {
            size_t gbase = ((size_t)tstep * NG + ujglob) * BB + ub;
            float pi = g_gxT[gbase];
            float pf = g_gxT[gbase + (size_t)1024 * BB];
            float pg = g_gxT[gbase + (size_t)2048 * BB];
            float po = g_gxT[gbase + (size_t)3072 * BB];
            if (tstep > 0) {
#pragma unroll
                for (int w = 0; w < 8; w++) {
                    int base = (w * 32 + ub) * 33 + uj;
                    pi += part[base];
                    pf += part[base + 8];
                    pg += part[base + 16];
                    po += part[base + 24];
                }
            }
            float gi = 1.0f / (1.0f + expf(-pi));
            float gf = 1.0f / (1.0f + expf(-pf));
            float gg = tanhf(pg);
            float go = 1.0f / (1.0f + expf(-po));
            c_state = gf * c_state + gi * gg;
            float h = go * tanhf(c_state);
            h_last = h;
            __nv_bfloat16 hh = __float2bfloat16(h);
            __nv_bfloat16 hl = __float2bfloat16(h - __bfloat162float(hh));
            size_t row = (size_t)(ub * 512 + tstep) * 3072;
            g_Abig[row + ujglob]        = hh;
            g_Abig[row + 1024 + ujglob] = hl;
            g_Abig[row + 2048 + ujglob] = hh;
        }
    }

    out[32768 + layer * 32768 + ub * 1024 + ujglob] = h_last;
    out[98304 + layer * 32768 + ub * 1024 + ujglob] = c_state;
    if (layer == 1) out[ub * 1024 + ujglob] = h_last;
}

// ---------------------------------------------------------------------------
extern "C" void kernel_launch(void* const* d_in, const int* in_sizes, int n_in,
                              void* d_out, int out_size)
{
    const float* x  = (const float*)d_in[0];
    const float* W0 = (const float*)d_in[1];
    const float* b0 = (const float*)d_in[2];
    const float* W1 = (const float*)d_in[3];
    const float* b1 = (const float*)d_in[4];
    float* out = (float*)d_out;

    cudaFuncSetAttribute(lstm_layer,
        cudaFuncAttributeMaxDynamicSharedMemorySize, LS_SMEM_BYTES);
    cudaFuncSetAttribute(gemm_x_bf16,
        cudaFuncAttributeMaxDynamicSharedMemorySize, GX_SMEM_WORDS * 4);

    __nv_bfloat16 *Abig, *B0big, *B1big;
    cudaGetSymbolAddress((void**)&Abig,  g_Abig);
    cudaGetSymbolAddress((void**)&B0big, g_B0big);
    cudaGetSymbolAddress((void**)&B1big, g_B1big);

    // splits: x -> Abig[0:1536); W0 x-part -> B0big; W1 x-part -> B1big
    split_x<<<(16384 * 512 + 255) / 256, 256>>>(x);
    split_w<<<(4096 * 512 + 255) / 256, 256>>>(W0, INF + HH, 512, B0big, 1536);
    split_w<<<(4096 * 1024 + 255) / 256, 256>>>(W1, HH + HH, 1024, B1big, 3072);

    // ---- Layer 0 ----
    gemm_x_bf16<<<dim3(64, 128), 256, GX_SMEM_WORDS * 4>>>(
        Abig, 3072, B0big, 1536, b0, 1536);
    init_kernel<<<1, 32>>>();
    lstm_layer<<<NCTA, 256, LS_SMEM_BYTES>>>(W0, INF + HH, INF, out, 0);

    // ---- Layer 1 (A = layer-0 h planes written by lstm_layer) ----
    gemm_x_bf16<<<dim3(64, 128), 256, GX_SMEM_WORDS * 4>>>(
        Abig, 3072, B1big, 3072, b1, 3072);
    init_kernel<<<1, 32>>>();
    lstm_layer<<<NCTA, 256, LS_SMEM_BYTES>>>(W1, HH + HH, HH, out, 1);
}

// round 8
// speedup vs baseline: 1.0177x; 1.0177x over previous
#include <cuda_runtime.h>
#include <cuda_bf16.h>
#include <math.h>
#include <stdint.h>

#define BB   32
#define SS   512
#define INF  512
#define HH   1024
#define NG   4096
#define NCTA 128

// Scratch (static device globals — allocation-free per harness rules)
__device__ float g_gxT[(size_t)SS * NG * BB];   // x-part gates, [s][n][b]
__device__ unsigned g_barCnt;
__device__ unsigned g_barRel;

// Interleaved hi/lo bf16 buffers (K-concatenation trick):
//   A row layout: [hi(0:D) | lo(D:2D) | hi(2D:3D)]  (D = 512 for x, 1024 for h)
//   B row layout: [hi | hi | lo]
// so C = A'·B'^T over K' = 3D equals the 3-term split product.
// g_Abig rows are m = b*512 + s; row stride 3072. Doubles as the recurrent
// h ping buffer: hi plane at col j, lo plane at col 1024+j, hi again 2048+j.
__device__ __nv_bfloat16 g_Abig[(size_t)16384 * 3072];
__device__ __nv_bfloat16 g_B0big[(size_t)4096 * 1536];
__device__ __nv_bfloat16 g_B1big[(size_t)4096 * 3072];

// ---------------------------------------------------------------------------
__global__ void init_kernel() {
    if (threadIdx.x == 0 && blockIdx.x == 0) { g_barCnt = 0u; g_barRel = 0u; }
}

// ---------------------------------------------------------------------------
__global__ void split_x(const float* __restrict__ x) {
    int idx = blockIdx.x * blockDim.x + threadIdx.x;   // 16384*512
    if (idx >= 16384 * 512) return;
    int r = idx >> 9, c = idx & 511;
    float v = x[idx];
    __nv_bfloat16 h = __float2bfloat16(v);
    __nv_bfloat16 l = __float2bfloat16(v - __bfloat162float(h));
    size_t base = (size_t)r * 3072;
    g_Abig[base + c]        = h;
    g_Abig[base + 512 + c]  = l;
    g_Abig[base + 1024 + c] = h;
}

// W x-part split: rows 4096, cols D; dst row = [hi | hi | lo], stride ldd.
__global__ void split_w(const float* __restrict__ W, int ldw, int cols,
                        __nv_bfloat16* __restrict__ dst, int ldd)
{
    int idx = blockIdx.x * blockDim.x + threadIdx.x;
    if (idx >= 4096 * cols) return;
    int r = idx / cols, c = idx - r * cols;
    float v = W[(size_t)r * ldw + c];
    __nv_bfloat16 h = __float2bfloat16(v);
    __nv_bfloat16 l = __float2bfloat16(v - __bfloat162float(h));
    size_t base = (size_t)r * ldd;
    dst[base + c]            = h;
    dst[base + cols + c]     = h;
    dst[base + 2 * cols + c] = l;
}

// ---------------------------------------------------------------------------
__device__ __forceinline__ void mma16816(float* d, const uint32_t* a,
                                         const uint32_t* b)
{
    asm volatile(
        "mma.sync.aligned.m16n8k16.row.col.f32.bf16.bf16.f32 "
        "{%0,%1,%2,%3}, {%4,%5,%6,%7}, {%8,%9}, {%0,%1,%2,%3};\n"
        : "+f"(d[0]), "+f"(d[1]), "+f"(d[2]), "+f"(d[3])
        : "r"(a[0]), "r"(a[1]), "r"(a[2]), "r"(a[3]), "r"(b[0]), "r"(b[1]));
}

__device__ __forceinline__ uint32_t smaddr(const void* p) {
    return (uint32_t)__cvta_generic_to_shared(p);
}
#define CP16(dst, src) \
    asm volatile("cp.async.cg.shared.global [%0], [%1], 16;" :: "r"(dst), "l"(src))
#define CPCOMMIT() asm volatile("cp.async.commit_group;")
#define CPWAIT(n)  asm volatile("cp.async.wait_group %0;" :: "n"(n))

// ---------------------------------------------------------------------------
// Generic bf16 GEMM: C[m][n] = sum_k A[m][k]*B[n][k] + bias[n % handled below],
// scattered to g_gxT. CTA tile 128(M)x64(N), warp tile 32x32, k-chunk 64,
// 2-stage cp.async double buffer, 2 CTAs/SM.
#define GX_SMEM_WORDS (2 * 128 * 36 + 2 * 64 * 36)

__global__ __launch_bounds__(256, 2) void gemm_x_bf16(
    const __nv_bfloat16* __restrict__ A, int lda,
    const __nv_bfloat16* __restrict__ B, int ldb,
    const float* __restrict__ bias, int K)
{
    extern __shared__ uint32_t smg[];
    uint32_t* smA = smg;                 // 2 stages x 128 x 36 words
    uint32_t* smB = smg + 2 * 128 * 36;  // 2 stages x  64 x 36 words

    const int tid  = threadIdx.x;
    const int n0   = blockIdx.x * 64;
    const int m0   = blockIdx.y * 128;
    const int wid  = tid >> 5, lane = tid & 31;
    const int wm   = (wid >> 1) * 32;
    const int wn   = (wid & 1) * 32;
    const int g    = lane >> 2, t = lane & 3;

    float acc[2][4][4];
#pragma unroll
    for (int mt = 0; mt < 2; mt++)
#pragma unroll
        for (int nt = 0; nt < 4; nt++)
#pragma unroll
            for (int i = 0; i < 4; i++) acc[mt][nt][i] = 0.0f;

    const int nch = K / 64;

    // stage loader: k-chunk 64 elems = 32 words = 8 x 16B per row
    auto stage = [&](int st, int k0) {
#pragma unroll
        for (int i = 0; i < 4; i++) {
            int q = i * 256 + tid;       // 0..1023 -> A 128 rows x 8 cps
            int r = q >> 3, c = q & 7;
            CP16(smaddr(&smA[(st * 128 + r) * 36 + c * 4]),
                 A + (size_t)(m0 + r) * lda + k0 + c * 8);
        }
#pragma unroll
        for (int i = 0; i < 2; i++) {
            int q = i * 256 + tid;       // 0..511 -> B 64 rows x 8 cps
            int r = q >> 3, c = q & 7;
            CP16(smaddr(&smB[(st * 64 + r) * 36 + c * 4]),
                 B + (size_t)(n0 + r) * ldb + k0 + c * 8);
        }
        CPCOMMIT();
    };

    stage(0, 0);

    for (int ch = 0; ch < nch; ch++) {
        if (ch + 1 < nch) { stage((ch + 1) & 1, (ch + 1) * 64); CPWAIT(1); }
        else              { CPWAIT(0); }
        __syncthreads();

        const uint32_t* uA = smA + (ch & 1) * 128 * 36;
        const uint32_t* uB = smB + (ch & 1) * 64 * 36;

#pragma unroll
        for (int kk = 0; kk < 4; kk++) {
            const int kb = kk * 8;
            uint32_t ah[2][4];
#pragma unroll
            for (int mt = 0; mt < 2; mt++) {
                int r0 = wm + mt * 16;
                ah[mt][0] = uA[(r0 + g)     * 36 + kb + t];
                ah[mt][1] = uA[(r0 + g + 8) * 36 + kb + t];
                ah[mt][2] = uA[(r0 + g)     * 36 + kb + t + 4];
                ah[mt][3] = uA[(r0 + g + 8) * 36 + kb + t + 4];
            }
#pragma unroll
            for (int nt = 0; nt < 4; nt++) {
                int c0 = wn + nt * 8;
                uint32_t bh[2];
                bh[0] = uB[(c0 + g) * 36 + kb + t];
                bh[1] = uB[(c0 + g) * 36 + kb + t + 4];
#pragma unroll
                for (int mt = 0; mt < 2; mt++)
                    mma16816(acc[mt][nt], ah[mt], bh);
            }
        }
        __syncthreads();
    }

    // epilogue: scatter to g_gxT[s][n][b] + bias
#pragma unroll
    for (int mt = 0; mt < 2; mt++) {
        int m1 = m0 + wm + mt * 16 + g;
        int m2 = m1 + 8;
        int b1 = m1 >> 9, s1 = m1 & 511;
        int b2 = m2 >> 9, s2 = m2 & 511;
#pragma unroll
        for (int nt = 0; nt < 4; nt++) {
            int n = n0 + wn + nt * 8 + 2 * t;
            float2 bv = *(const float2*)&bias[n];
            size_t o1 = ((size_t)s1 * NG + n) * BB + b1;
            size_t o2 = ((size_t)s2 * NG + n) * BB + b2;
            g_gxT[o1]      = acc[mt][nt][0] + bv.x;
            g_gxT[o1 + BB] = acc[mt][nt][1] + bv.y;
            g_gxT[o2]      = acc[mt][nt][2] + bv.x;
            g_gxT[o2 + BB] = acc[mt][nt][3] + bv.y;
        }
    }
}

// ---------------------------------------------------------------------------
// Persistent recurrent kernel, HMMA version (proven in R6). 128 CTAs x 256
// thr, 1 CTA/SM. h hi/lo planes live in g_Abig (cols [0,1024) hi,
// [1024,2048) lo), row = b*512 + t, row stride 3072.
#define LS_W_L   16512
#define LS_HC_H  33024
#define LS_HC_L  37248
#define LS_PART  41472
#define LS_SMEM_BYTES (49920 * 4)

__global__ __launch_bounds__(256, 1) void lstm_layer(
    const float* __restrict__ W, int ldw, int Din,
    float* __restrict__ out, int layer)
{
    extern __shared__ uint32_t smu[];
    uint32_t* Wsh = smu;
    uint32_t* Wsl = smu + LS_W_L;
    uint32_t* Hh  = smu + LS_HC_H;
    uint32_t* Hl  = smu + LS_HC_L;
    float*    part = (float*)(smu + LS_PART);

    const int tid  = threadIdx.x;
    const int cta  = blockIdx.x;
    const int j0   = cta * 8;
    const int wid  = tid >> 5, lane = tid & 31;
    const int g    = lane >> 2, t4 = lane & 3;

    // ---- Load + split recurrent W slice once (32 rows x 1024 k) ----
    for (int i = 0; i < 64; i++) {
        int q  = i * 256 + tid;
        int l  = q >> 9;
        int wk = q & 511;
        int gate = l >> 3, jj = l & 7;
        int n = gate * 1024 + j0 + jj;
        float2 v = *(const float2*)(W + (size_t)n * ldw + Din + wk * 2);
        __nv_bfloat16 hx = __float2bfloat16(v.x);
        __nv_bfloat16 hy = __float2bfloat16(v.y);
        __nv_bfloat16 lx = __float2bfloat16(v.x - __bfloat162float(hx));
        __nv_bfloat16 ly = __float2bfloat16(v.y - __bfloat162float(hy));
        Wsh[l * 516 + wk] = (uint32_t)__bfloat16_as_ushort(hx)
                          | ((uint32_t)__bfloat16_as_ushort(hy) << 16);
        Wsl[l * 516 + wk] = (uint32_t)__bfloat16_as_ushort(lx)
                          | ((uint32_t)__bfloat16_as_ushort(ly) << 16);
    }

    const int ub = tid & 31;
    const int uj = tid >> 5;
    const int ujglob = j0 + uj;

    float c_state = 0.0f;
    float h_last  = 0.0f;
    unsigned round = 0;

    __syncthreads();

    for (int tstep = 0; tstep < SS; tstep++) {
        // ---- grid barrier ----
        round++;
        __syncthreads();
        if (tid == 0) {
            __threadfence();
            unsigned arrived = atomicAdd(&g_barCnt, 1u) + 1u;
            if (arrived == round * NCTA) {
                atomicExch(&g_barRel, round);
            } else {
                volatile unsigned* rel = &g_barRel;
                while (*rel < round) {}
            }
            __threadfence();
        }
        __syncthreads();

        float acc[2][4][4];
#pragma unroll
        for (int mt = 0; mt < 2; mt++)
#pragma unroll
            for (int nt = 0; nt < 4; nt++)
#pragma unroll
                for (int i = 0; i < 4; i++) acc[mt][nt][i] = 0.0f;

        if (tstep > 0) {
            for (int cch = 0; cch < 4; cch++) {
                __syncthreads();
#pragma unroll
                for (int i = 0; i < 4; i++) {
                    int q  = i * 256 + tid;
                    int b  = q >> 5, u4 = q & 31;
                    size_t row = (size_t)(b * 512 + tstep - 1) * 3072;
                    size_t bh_ = row + cch * 256;
                    size_t bl_ = row + 1024 + cch * 256;
                    *(uint4*)&Hh[b * 132 + u4 * 4] =
                        __ldcg((const uint4*)(g_Abig + bh_) + u4);
                    *(uint4*)&Hl[b * 132 + u4 * 4] =
                        __ldcg((const uint4*)(g_Abig + bl_) + u4);
                }
                __syncthreads();

#pragma unroll
                for (int s = 0; s < 2; s++) {
                    int ks = wid * 2 + s;
                    int aw = ks * 8 + t4;
                    int bw = cch * 128 + ks * 8 + t4;
                    uint32_t ah[2][4], al[2][4];
#pragma unroll
                    for (int mt = 0; mt < 2; mt++) {
                        int r = mt * 16 + g;
                        ah[mt][0] = Hh[r * 132 + aw];
                        ah[mt][1] = Hh[(r + 8) * 132 + aw];
                        ah[mt][2] = Hh[r * 132 + aw + 4];
                        ah[mt][3] = Hh[(r + 8) * 132 + aw + 4];
                        al[mt][0] = Hl[r * 132 + aw];
                        al[mt][1] = Hl[(r + 8) * 132 + aw];
                        al[mt][2] = Hl[r * 132 + aw + 4];
                        al[mt][3] = Hl[(r + 8) * 132 + aw + 4];
                    }
#pragma unroll
                    for (int nt = 0; nt < 4; nt++) {
                        int rn = nt * 8 + g;
                        uint32_t bh[2], bl[2];
                        bh[0] = Wsh[rn * 516 + bw];
                        bh[1] = Wsh[rn * 516 + bw + 4];
                        bl[0] = Wsl[rn * 516 + bw];
                        bl[1] = Wsl[rn * 516 + bw + 4];
#pragma unroll
                        for (int mt = 0; mt < 2; mt++) {
                            mma16816(acc[mt][nt], ah[mt], bh);
                            mma16816(acc[mt][nt], ah[mt], bl);
                            mma16816(acc[mt][nt], al[mt], bh);
                        }
                    }
                }
            }
            // store partials (scalar — stride 33 is odd; float2 traps)
#pragma unroll
            for (int mt = 0; mt < 2; mt++) {
                int b = mt * 16 + g;
#pragma unroll
                for (int nt = 0; nt < 4; nt++) {
                    int l = nt * 8 + 2 * t4;
                    part[(wid * 32 + b) * 33 + l]     = acc[mt][nt][0];
                    part[(wid * 32 + b) * 33 + l + 1] = acc[mt][nt][1];
                    part[(wid * 32 + b + 8) * 33 + l]     = acc[mt][nt][2];
                    part[(wid * 32 + b + 8) * 33 + l + 1] = acc[mt][nt][3];
                }
            }
            __syncthreads();
        }

        // ---- reduce + activations + state update ----
        {
            size_t gbase = ((size_t)tstep * NG + ujglob) * BB + ub;
            float pi = g_gxT[gbase];
            float pf = g_gxT[gbase + (size_t)1024 * BB];
            float pg = g_gxT[gbase + (size_t)2048 * BB];
            float po = g_gxT[gbase + (size_t)3072 * BB];
            if (tstep > 0) {
#pragma unroll
                for (int w = 0; w < 8; w++) {
                    int base = (w * 32 + ub) * 33 + uj;
                    pi += part[base];
                    pf += part[base + 8];
                    pg += part[base + 16];
                    po += part[base + 24];
                }
            }
            float gi = 1.0f / (1.0f + expf(-pi));
            float gf = 1.0f / (1.0f + expf(-pf));
            float gg = tanhf(pg);
            float go = 1.0f / (1.0f + expf(-po));
            c_state = gf * c_state + gi * gg;
            float h = go * tanhf(c_state);
            h_last = h;
            __nv_bfloat16 hh = __float2bfloat16(h);
            __nv_bfloat16 hl = __float2bfloat16(h - __bfloat162float(hh));
            size_t row = (size_t)(ub * 512 + tstep) * 3072;
            g_Abig[row + ujglob]        = hh;
            g_Abig[row + 1024 + ujglob] = hl;
            g_Abig[row + 2048 + ujglob] = hh;
        }
    }

    out[32768 + layer * 32768 + ub * 1024 + ujglob] = h_last;
    out[98304 + layer * 32768 + ub * 1024 + ujglob] = c_state;
    if (layer == 1) out[ub * 1024 + ujglob] = h_last;
}

// ---------------------------------------------------------------------------
extern "C" void kernel_launch(void* const* d_in, const int* in_sizes, int n_in,
                              void* d_out, int out_size)
{
    const float* x  = (const float*)d_in[0];
    const float* W0 = (const float*)d_in[1];
    const float* b0 = (const float*)d_in[2];
    const float* W1 = (const float*)d_in[3];
    const float* b1 = (const float*)d_in[4];
    float* out = (float*)d_out;

    cudaFuncSetAttribute(lstm_layer,
        cudaFuncAttributeMaxDynamicSharedMemorySize, LS_SMEM_BYTES);
    cudaFuncSetAttribute(gemm_x_bf16,
        cudaFuncAttributeMaxDynamicSharedMemorySize, GX_SMEM_WORDS * 4);

    __nv_bfloat16 *Abig, *B0big, *B1big;
    cudaGetSymbolAddress((void**)&Abig,  g_Abig);
    cudaGetSymbolAddress((void**)&B0big, g_B0big);
    cudaGetSymbolAddress((void**)&B1big, g_B1big);

    // splits: x -> Abig[0:1536); W0 x-part -> B0big; W1 x-part -> B1big
    split_x<<<(16384 * 512 + 255) / 256, 256>>>(x);
    split_w<<<(4096 * 512 + 255) / 256, 256>>>(W0, INF + HH, 512, B0big, 1536);
    split_w<<<(4096 * 1024 + 255) / 256, 256>>>(W1, HH + HH, 1024, B1big, 3072);

    // ---- Layer 0 ----
    gemm_x_bf16<<<dim3(64, 128), 256, GX_SMEM_WORDS * 4>>>(
        Abig, 3072, B0big, 1536, b0, 1536);
    init_kernel<<<1, 32>>>();
    lstm_layer<<<NCTA, 256, LS_SMEM_BYTES>>>(W0, INF + HH, INF, out, 0);

    // ---- Layer 1 (A = layer-0 h planes written by lstm_layer) ----
    gemm_x_bf16<<<dim3(64, 128), 256, GX_SMEM_WORDS * 4>>>(
        Abig, 3072, B1big, 3072, b1, 3072);
    init_kernel<<<1, 32>>>();
    lstm_layer<<<NCTA, 256, LS_SMEM_BYTES>>>(W1, HH + HH, HH, out, 1);
}

// round 9
// speedup vs baseline: 1.0205x; 1.0027x over previous
#include <cuda_runtime.h>
#include <cuda_bf16.h>
#include <math.h>
#include <stdint.h>

#define BB   32
#define SS   512
#define INF  512
#define HH   1024
#define NG   4096
#define NCTA 128

// Scratch (static device globals — allocation-free per harness rules)
__device__ float g_gxT[(size_t)SS * NG * BB];   // x-part gates, [s][n][b]
__device__ unsigned g_barCnt;
__device__ unsigned g_barRel;

// Interleaved hi/lo bf16 buffers (K-concatenation):
//   A row: [hi(0:D) | lo | hi]  (D = 512 for x, 1024 for h), B row: [hi | hi | lo]
__device__ __nv_bfloat16 g_Abig[(size_t)16384 * 3072];
__device__ __nv_bfloat16 g_B0big[(size_t)4096 * 1536];
__device__ __nv_bfloat16 g_B1big[(size_t)4096 * 3072];

// ---------------------------------------------------------------------------
__global__ void init_kernel() {
    if (threadIdx.x == 0 && blockIdx.x == 0) { g_barCnt = 0u; g_barRel = 0u; }
}

// ---------------------------------------------------------------------------
__global__ void split_x(const float* __restrict__ x) {
    int idx = blockIdx.x * blockDim.x + threadIdx.x;
    if (idx >= 16384 * 512) return;
    int r = idx >> 9, c = idx & 511;
    float v = x[idx];
    __nv_bfloat16 h = __float2bfloat16(v);
    __nv_bfloat16 l = __float2bfloat16(v - __bfloat162float(h));
    size_t base = (size_t)r * 3072;
    g_Abig[base + c]        = h;
    g_Abig[base + 512 + c]  = l;
    g_Abig[base + 1024 + c] = h;
}

__global__ void split_w(const float* __restrict__ W, int ldw, int cols,
                        __nv_bfloat16* __restrict__ dst, int ldd)
{
    int idx = blockIdx.x * blockDim.x + threadIdx.x;
    if (idx >= 4096 * cols) return;
    int r = idx / cols, c = idx - r * cols;
    float v = W[(size_t)r * ldw + c];
    __nv_bfloat16 h = __float2bfloat16(v);
    __nv_bfloat16 l = __float2bfloat16(v - __bfloat162float(h));
    size_t base = (size_t)r * ldd;
    dst[base + c]            = h;
    dst[base + cols + c]     = h;
    dst[base + 2 * cols + c] = l;
}

// ---------------------------------------------------------------------------
__device__ __forceinline__ void mma16816(float* d, const uint32_t* a,
                                         const uint32_t* b)
{
    asm volatile(
        "mma.sync.aligned.m16n8k16.row.col.f32.bf16.bf16.f32 "
        "{%0,%1,%2,%3}, {%4,%5,%6,%7}, {%8,%9}, {%0,%1,%2,%3};\n"
        : "+f"(d[0]), "+f"(d[1]), "+f"(d[2]), "+f"(d[3])
        : "r"(a[0]), "r"(a[1]), "r"(a[2]), "r"(a[3]), "r"(b[0]), "r"(b[1]));
}

__device__ __forceinline__ void ldsm4(uint32_t* r, uint32_t addr) {
    asm volatile(
        "ldmatrix.sync.aligned.m8n8.x4.shared.b16 {%0,%1,%2,%3}, [%4];"
        : "=r"(r[0]), "=r"(r[1]), "=r"(r[2]), "=r"(r[3]) : "r"(addr));
}

__device__ __forceinline__ uint32_t smaddr(const void* p) {
    return (uint32_t)__cvta_generic_to_shared(p);
}
#define CP16(dst, src) \
    asm volatile("cp.async.cg.shared.global [%0], [%1], 16;" :: "r"(dst), "l"(src))
#define CPCOMMIT() asm volatile("cp.async.commit_group;")
#define CPWAIT(n)  asm volatile("cp.async.wait_group %0;" :: "n"(n))

// ---------------------------------------------------------------------------
// bf16 GEMM with ldmatrix fragment loads + 3-stage cp.async pipeline.
// CTA tile 128(M)x64(N), 8 warps (warp tile 32x32), k-chunk 64, 2 CTAs/SM.
// Stage layout: [A 128x36 | B 64x36] words; 3 stages = 82944 B.
#define STW        (192 * 36)          // words per stage
#define GX_SMEM_BYTES (3 * STW * 4)

__global__ __launch_bounds__(256, 2) void gemm_x_bf16(
    const __nv_bfloat16* __restrict__ A, int lda,
    const __nv_bfloat16* __restrict__ B, int ldb,
    const float* __restrict__ bias, int K)
{
    extern __shared__ uint32_t smg[];

    const int tid  = threadIdx.x;
    const int n0   = blockIdx.x * 64;
    const int m0   = blockIdx.y * 128;
    const int wid  = tid >> 5, lane = tid & 31;
    const int wm   = (wid >> 1) * 32;
    const int wn   = (wid & 1) * 32;
    const int g    = lane >> 2, t = lane & 3;

    const uint32_t smb = smaddr(smg);

    // per-lane ldmatrix base word offsets (within a stage)
    const int aoffw = (wm + (lane & 15)) * 36 + (lane >> 4) * 4;
    const int boffw = 128 * 36
                    + (wn + ((lane >> 4) & 1) * 8 + (lane & 7)) * 36
                    + ((lane >> 3) & 1) * 4;

    float acc[2][4][4];
#pragma unroll
    for (int mt = 0; mt < 2; mt++)
#pragma unroll
        for (int nt = 0; nt < 4; nt++)
#pragma unroll
            for (int i = 0; i < 4; i++) acc[mt][nt][i] = 0.0f;

    const int nch = K / 64;

    auto stage = [&](int st, int k0) {
        uint32_t base = smb + st * (STW * 4);
#pragma unroll
        for (int i = 0; i < 4; i++) {
            int q = i * 256 + tid;               // A: 128 rows x 8 cps
            int r = q >> 3, c = q & 7;
            CP16(base + (r * 36 + c * 4) * 4,
                 A + (size_t)(m0 + r) * lda + k0 + c * 8);
        }
#pragma unroll
        for (int i = 0; i < 2; i++) {
            int q = i * 256 + tid;               // B: 64 rows x 8 cps
            int r = q >> 3, c = q & 7;
            CP16(base + (128 * 36 + r * 36 + c * 4) * 4,
                 B + (size_t)(n0 + r) * ldb + k0 + c * 8);
        }
        CPCOMMIT();
    };

    stage(0, 0);
    stage(1, 64);

    for (int ch = 0; ch < nch; ch++) {
        CPWAIT(1);
        __syncthreads();
        if (ch + 2 < nch) stage((ch + 2) % 3, (ch + 2) * 64);

        const uint32_t sA = smb + (ch % 3) * (STW * 4) + aoffw * 4;
        const uint32_t sB = smb + (ch % 3) * (STW * 4) + boffw * 4;

#pragma unroll
        for (int kk = 0; kk < 4; kk++) {
            uint32_t a0[4], a1[4], b0[4], b1[4];
            ldsm4(a0, sA + kk * 32);                  // A rows [wm,wm+16)
            ldsm4(a1, sA + 16 * 36 * 4 + kk * 32);    // A rows [wm+16,wm+32)
            ldsm4(b0, sB + kk * 32);                  // B rows [wn,wn+16)
            ldsm4(b1, sB + 16 * 36 * 4 + kk * 32);    // B rows [wn+16,wn+32)
            mma16816(acc[0][0], a0, b0);
            mma16816(acc[1][0], a1, b0);
            mma16816(acc[0][1], a0, b0 + 2);
            mma16816(acc[1][1], a1, b0 + 2);
            mma16816(acc[0][2], a0, b1);
            mma16816(acc[1][2], a1, b1);
            mma16816(acc[0][3], a0, b1 + 2);
            mma16816(acc[1][3], a1, b1 + 2);
        }
    }

    // epilogue: scatter to g_gxT[s][n][b] + bias
#pragma unroll
    for (int mt = 0; mt < 2; mt++) {
        int m1 = m0 + wm + mt * 16 + g;
        int m2 = m1 + 8;
        int b1 = m1 >> 9, s1 = m1 & 511;
        int b2 = m2 >> 9, s2 = m2 & 511;
#pragma unroll
        for (int nt = 0; nt < 4; nt++) {
            int n = n0 + wn + nt * 8 + 2 * t;
            float2 bv = *(const float2*)&bias[n];
            size_t o1 = ((size_t)s1 * NG + n) * BB + b1;
            size_t o2 = ((size_t)s2 * NG + n) * BB + b2;
            g_gxT[o1]      = acc[mt][nt][0] + bv.x;
            g_gxT[o1 + BB] = acc[mt][nt][1] + bv.y;
            g_gxT[o2]      = acc[mt][nt][2] + bv.x;
            g_gxT[o2 + BB] = acc[mt][nt][3] + bv.y;
        }
    }
}

// ---------------------------------------------------------------------------
// Persistent recurrent kernel, HMMA version (proven). 128 CTAs x 256 thr,
// 1 CTA/SM. h hi/lo planes in g_Abig (cols [0,1024) hi, [1024,2048) lo),
// row = b*512 + t, row stride 3072.
#define LS_W_L   16512
#define LS_HC_H  33024
#define LS_HC_L  37248
#define LS_PART  41472
#define LS_SMEM_BYTES (49920 * 4)

__global__ __launch_bounds__(256, 1) void lstm_layer(
    const float* __restrict__ W, int ldw, int Din,
    float* __restrict__ out, int layer)
{
    extern __shared__ uint32_t smu[];
    uint32_t* Wsh = smu;
    uint32_t* Wsl = smu + LS_W_L;
    uint32_t* Hh  = smu + LS_HC_H;
    uint32_t* Hl  = smu + LS_HC_L;
    float*    part = (float*)(smu + LS_PART);

    const int tid  = threadIdx.x;
    const int cta  = blockIdx.x;
    const int j0   = cta * 8;
    const int wid  = tid >> 5, lane = tid & 31;
    const int g    = lane >> 2, t4 = lane & 3;

    for (int i = 0; i < 64; i++) {
        int q  = i * 256 + tid;
        int l  = q >> 9;
        int wk = q & 511;
        int gate = l >> 3, jj = l & 7;
        int n = gate * 1024 + j0 + jj;
        float2 v = *(const float2*)(W + (size_t)n * ldw + Din + wk * 2);
        __nv_bfloat16 hx = __float2bfloat16(v.x);
        __nv_bfloat16 hy = __float2bfloat16(v.y);
        __nv_bfloat16 lx = __float2bfloat16(v.x - __bfloat162float(hx));
        __nv_bfloat16 ly = __float2bfloat16(v.y - __bfloat162float(hy));
        Wsh[l * 516 + wk] = (uint32_t)__bfloat16_as_ushort(hx)
                          | ((uint32_t)__bfloat16_as_ushort(hy) << 16);
        Wsl[l * 516 + wk] = (uint32_t)__bfloat16_as_ushort(lx)
                          | ((uint32_t)__bfloat16_as_ushort(ly) << 16);
    }

    const int ub = tid & 31;
    const int uj = tid >> 5;
    const int ujglob = j0 + uj;

    float c_state = 0.0f;
    float h_last  = 0.0f;
    unsigned round = 0;

    __syncthreads();

    for (int tstep = 0; tstep < SS; tstep++) {
        round++;
        __syncthreads();
        if (tid == 0) {
            __threadfence();
            unsigned arrived = atomicAdd(&g_barCnt, 1u) + 1u;
            if (arrived == round * NCTA) {
                atomicExch(&g_barRel, round);
            } else {
                volatile unsigned* rel = &g_barRel;
                while (*rel < round) {}
            }
            __threadfence();
        }
        __syncthreads();

        float acc[2][4][4];
#pragma unroll
        for (int mt = 0; mt < 2; mt++)
#pragma unroll
            for (int nt = 0; nt < 4; nt++)
#pragma unroll
                for (int i = 0; i < 4; i++) acc[mt][nt][i] = 0.0f;

        if (tstep > 0) {
            for (int cch = 0; cch < 4; cch++) {
                __syncthreads();
#pragma unroll
                for (int i = 0; i < 4; i++) {
                    int q  = i * 256 + tid;
                    int b  = q >> 5, u4 = q & 31;
                    size_t row = (size_t)(b * 512 + tstep - 1) * 3072;
                    size_t bh_ = row + cch * 256;
                    size_t bl_ = row + 1024 + cch * 256;
                    *(uint4*)&Hh[b * 132 + u4 * 4] =
                        __ldcg((const uint4*)(g_Abig + bh_) + u4);
                    *(uint4*)&Hl[b * 132 + u4 * 4] =
                        __ldcg((const uint4*)(g_Abig + bl_) + u4);
                }
                __syncthreads();

#pragma unroll
                for (int s = 0; s < 2; s++) {
                    int ks = wid * 2 + s;
                    int aw = ks * 8 + t4;
                    int bw = cch * 128 + ks * 8 + t4;
                    uint32_t ah[2][4], al[2][4];
#pragma unroll
                    for (int mt = 0; mt < 2; mt++) {
                        int r = mt * 16 + g;
                        ah[mt][0] = Hh[r * 132 + aw];
                        ah[mt][1] = Hh[(r + 8) * 132 + aw];
                        ah[mt][2] = Hh[r * 132 + aw + 4];
                        ah[mt][3] = Hh[(r + 8) * 132 + aw + 4];
                        al[mt][0] = Hl[r * 132 + aw];
                        al[mt][1] = Hl[(r + 8) * 132 + aw];
                        al[mt][2] = Hl[r * 132 + aw + 4];
                        al[mt][3] = Hl[(r + 8) * 132 + aw + 4];
                    }
#pragma unroll
                    for (int nt = 0; nt < 4; nt++) {
                        int rn = nt * 8 + g;
                        uint32_t bh[2], bl[2];
                        bh[0] = Wsh[rn * 516 + bw];
                        bh[1] = Wsh[rn * 516 + bw + 4];
                        bl[0] = Wsl[rn * 516 + bw];
                        bl[1] = Wsl[rn * 516 + bw + 4];
#pragma unroll
                        for (int mt = 0; mt < 2; mt++) {
                            mma16816(acc[mt][nt], ah[mt], bh);
                            mma16816(acc[mt][nt], ah[mt], bl);
                            mma16816(acc[mt][nt], al[mt], bh);
                        }
                    }
                }
            }
#pragma unroll
            for (int mt = 0; mt < 2; mt++) {
                int b = mt * 16 + g;
#pragma unroll
                for (int nt = 0; nt < 4; nt++) {
                    int l = nt * 8 + 2 * t4;
                    part[(wid * 32 + b) * 33 + l]     = acc[mt][nt][0];
                    part[(wid * 32 + b) * 33 + l + 1] = acc[mt][nt][1];
                    part[(wid * 32 + b + 8) * 33 + l]     = acc[mt][nt][2];
                    part[(wid * 32 + b + 8) * 33 + l + 1] = acc[mt][nt][3];
                }
            }
            __syncthreads();
        }

        {
            size_t gbase = ((size_t)tstep * NG + ujglob) * BB + ub;
            float pi = g_gxT[gbase];
            float pf = g_gxT[gbase + (size_t)1024 * BB];
            float pg = g_gxT[gbase + (size_t)2048 * BB];
            float po = g_gxT[gbase + (size_t)3072 * BB];
            if (tstep > 0) {
#pragma unroll
                for (int w = 0; w < 8; w++) {
                    int base = (w * 32 + ub) * 33 + uj;
                    pi += part[base];
                    pf += part[base + 8];
                    pg += part[base + 16];
                    po += part[base + 24];
                }
            }
            float gi = 1.0f / (1.0f + expf(-pi));
            float gf = 1.0f / (1.0f + expf(-pf));
            float gg = tanhf(pg);
            float go = 1.0f / (1.0f + expf(-po));
            c_state = gf * c_state + gi * gg;
            float h = go * tanhf(c_state);
            h_last = h;
            __nv_bfloat16 hh = __float2bfloat16(h);
            __nv_bfloat16 hl = __float2bfloat16(h - __bfloat162float(hh));
            size_t row = (size_t)(ub * 512 + tstep) * 3072;
            g_Abig[row + ujglob]        = hh;
            g_Abig[row + 1024 + ujglob] = hl;
            g_Abig[row + 2048 + ujglob] = hh;
        }
    }

    out[32768 + layer * 32768 + ub * 1024 + ujglob] = h_last;
    out[98304 + layer * 32768 + ub * 1024 + ujglob] = c_state;
    if (layer == 1) out[ub * 1024 + ujglob] = h_last;
}

// ---------------------------------------------------------------------------
extern "C" void kernel_launch(void* const* d_in, const int* in_sizes, int n_in,
                              void* d_out, int out_size)
{
    const float* x  = (const float*)d_in[0];
    const float* W0 = (const float*)d_in[1];
    const float* b0 = (const float*)d_in[2];
    const float* W1 = (const float*)d_in[3];
    const float* b1 = (const float*)d_in[4];
    float* out = (float*)d_out;

    cudaFuncSetAttribute(lstm_layer,
        cudaFuncAttributeMaxDynamicSharedMemorySize, LS_SMEM_BYTES);
    cudaFuncSetAttribute(gemm_x_bf16,
        cudaFuncAttributeMaxDynamicSharedMemorySize, GX_SMEM_BYTES);

    __nv_bfloat16 *Abig, *B0big, *B1big;
    cudaGetSymbolAddress((void**)&Abig,  g_Abig);
    cudaGetSymbolAddress((void**)&B0big, g_B0big);
    cudaGetSymbolAddress((void**)&B1big, g_B1big);

    split_x<<<(16384 * 512 + 255) / 256, 256>>>(x);
    split_w<<<(4096 * 512 + 255) / 256, 256>>>(W0, INF + HH, 512, B0big, 1536);
    split_w<<<(4096 * 1024 + 255) / 256, 256>>>(W1, HH + HH, 1024, B1big, 3072);

    // ---- Layer 0 ----
    gemm_x_bf16<<<dim3(64, 128), 256, GX_SMEM_BYTES>>>(
        Abig, 3072, B0big, 1536, b0, 1536);
    init_kernel<<<1, 32>>>();
    lstm_layer<<<NCTA, 256, LS_SMEM_BYTES>>>(W0, INF + HH, INF, out, 0);

    // ---- Layer 1 (A = layer-0 h planes written by lstm_layer) ----
    gemm_x_bf16<<<dim3(64, 128), 256, GX_SMEM_BYTES>>>(
        Abig, 3072, B1big, 3072, b1, 3072);
    init_kernel<<<1, 32>>>();
    lstm_layer<<<NCTA, 256, LS_SMEM_BYTES>>>(W1, HH + HH, HH, out, 1);
}

// round 10
// speedup vs baseline: 1.1509x; 1.1278x over previous
#include <cuda_runtime.h>
#include <cuda_bf16.h>
#include <math.h>
#include <stdint.h>

#define BB   32
#define SS   512
#define INF  512
#define HH   1024
#define NG   4096
#define NCTA 128

__device__ float g_gxT[(size_t)SS * NG * BB];   // x-part gates, [s][n][b]
__device__ unsigned g_barCnt;
__device__ unsigned g_barRel;

// K-concat hi/lo bf16 buffers. A row: [hi | lo | hi], B row: [hi | hi | lo].
// g_Abig doubles as recurrent h buffer: row = b*512 + t, stride 3072.
__device__ __nv_bfloat16 g_Abig[(size_t)16384 * 3072];
__device__ __nv_bfloat16 g_B0big[(size_t)4096 * 1536];
__device__ __nv_bfloat16 g_B1big[(size_t)4096 * 3072];

// ---------------------------------------------------------------------------
__global__ void split_x(const float* __restrict__ x) {
    int idx = blockIdx.x * blockDim.x + threadIdx.x;
    if (idx == 0) { g_barCnt = 0u; g_barRel = 0u; }
    if (idx >= 16384 * 512) return;
    int r = idx >> 9, c = idx & 511;
    float v = x[idx];
    __nv_bfloat16 h = __float2bfloat16(v);
    __nv_bfloat16 l = __float2bfloat16(v - __bfloat162float(h));
    size_t base = (size_t)r * 3072;
    g_Abig[base + c]        = h;
    g_Abig[base + 512 + c]  = l;
    g_Abig[base + 1024 + c] = h;
}

__global__ void split_w(const float* __restrict__ W, int ldw, int cols,
                        __nv_bfloat16* __restrict__ dst, int ldd)
{
    int idx = blockIdx.x * blockDim.x + threadIdx.x;
    if (idx >= 4096 * cols) return;
    int r = idx / cols, c = idx - r * cols;
    float v = W[(size_t)r * ldw + c];
    __nv_bfloat16 h = __float2bfloat16(v);
    __nv_bfloat16 l = __float2bfloat16(v - __bfloat162float(h));
    size_t base = (size_t)r * ldd;
    dst[base + c]            = h;
    dst[base + cols + c]     = h;
    dst[base + 2 * cols + c] = l;
}

// ---------------------------------------------------------------------------
__device__ __forceinline__ void mma16816(float* d, const uint32_t* a,
                                         const uint32_t* b)
{
    asm volatile(
        "mma.sync.aligned.m16n8k16.row.col.f32.bf16.bf16.f32 "
        "{%0,%1,%2,%3}, {%4,%5,%6,%7}, {%8,%9}, {%0,%1,%2,%3};\n"
        : "+f"(d[0]), "+f"(d[1]), "+f"(d[2]), "+f"(d[3])
        : "r"(a[0]), "r"(a[1]), "r"(a[2]), "r"(a[3]), "r"(b[0]), "r"(b[1]));
}

__device__ __forceinline__ void ldsm4(uint32_t* r, uint32_t addr) {
    asm volatile(
        "ldmatrix.sync.aligned.m8n8.x4.shared.b16 {%0,%1,%2,%3}, [%4];"
        : "=r"(r[0]), "=r"(r[1]), "=r"(r[2]), "=r"(r[3]) : "r"(addr));
}

__device__ __forceinline__ uint32_t smaddr(const void* p) {
    return (uint32_t)__cvta_generic_to_shared(p);
}
#define CP16(dst, src) \
    asm volatile("cp.async.cg.shared.global [%0], [%1], 16;" :: "r"(dst), "l"(src))
#define CPCOMMIT() asm volatile("cp.async.commit_group;")
template<int N> __device__ __forceinline__ void cpwaitc() {
    asm volatile("cp.async.wait_group %0;" :: "n"(N));
}

// ---------------------------------------------------------------------------
// bf16 GEMM (x-projection): ldmatrix frags + 3-stage cp.async. CTA 128x64,
// 8 warps (32x32), k-chunk 64, 2 CTAs/SM. FIXED tail wait (R9 race).
#define STW        (192 * 36)
#define GX_SMEM_BYTES (3 * STW * 4)

__global__ __launch_bounds__(256, 2) void gemm_x_bf16(
    const __nv_bfloat16* __restrict__ A, int lda,
    const __nv_bfloat16* __restrict__ B, int ldb,
    const float* __restrict__ bias, int K)
{
    extern __shared__ uint32_t smg[];

    const int tid  = threadIdx.x;
    const int n0   = blockIdx.x * 64;
    const int m0   = blockIdx.y * 128;
    const int wid  = tid >> 5, lane = tid & 31;
    const int wm   = (wid >> 1) * 32;
    const int wn   = (wid & 1) * 32;
    const int g    = lane >> 2, t = lane & 3;

    const uint32_t smb = smaddr(smg);

    const int aoffw = (wm + (lane & 15)) * 36 + (lane >> 4) * 4;
    const int boffw = 128 * 36
                    + (wn + ((lane >> 4) & 1) * 8 + (lane & 7)) * 36
                    + ((lane >> 3) & 1) * 4;

    float acc[2][4][4];
#pragma unroll
    for (int mt = 0; mt < 2; mt++)
#pragma unroll
        for (int nt = 0; nt < 4; nt++)
#pragma unroll
            for (int i = 0; i < 4; i++) acc[mt][nt][i] = 0.0f;

    const int nch = K / 64;

    auto stage = [&](int st, int k0) {
        uint32_t base = smb + st * (STW * 4);
#pragma unroll
        for (int i = 0; i < 4; i++) {
            int q = i * 256 + tid;
            int r = q >> 3, c = q & 7;
            CP16(base + (r * 36 + c * 4) * 4,
                 A + (size_t)(m0 + r) * lda + k0 + c * 8);
        }
#pragma unroll
        for (int i = 0; i < 2; i++) {
            int q = i * 256 + tid;
            int r = q >> 3, c = q & 7;
            CP16(base + (128 * 36 + r * 36 + c * 4) * 4,
                 B + (size_t)(n0 + r) * ldb + k0 + c * 8);
        }
        CPCOMMIT();
    };

    stage(0, 0);
    stage(1, 64);

    for (int ch = 0; ch < nch; ch++) {
        if (ch + 1 < nch) cpwaitc<1>(); else cpwaitc<0>();   // tail fix
        __syncthreads();
        if (ch + 2 < nch) stage((ch + 2) % 3, (ch + 2) * 64);

        const uint32_t sA = smb + (ch % 3) * (STW * 4) + aoffw * 4;
        const uint32_t sB = smb + (ch % 3) * (STW * 4) + boffw * 4;

#pragma unroll
        for (int kk = 0; kk < 4; kk++) {
            uint32_t a0[4], a1[4], b0[4], b1[4];
            ldsm4(a0, sA + kk * 32);
            ldsm4(a1, sA + 16 * 36 * 4 + kk * 32);
            ldsm4(b0, sB + kk * 32);
            ldsm4(b1, sB + 16 * 36 * 4 + kk * 32);
            mma16816(acc[0][0], a0, b0);
            mma16816(acc[1][0], a1, b0);
            mma16816(acc[0][1], a0, b0 + 2);
            mma16816(acc[1][1], a1, b0 + 2);
            mma16816(acc[0][2], a0, b1);
            mma16816(acc[1][2], a1, b1);
            mma16816(acc[0][3], a0, b1 + 2);
            mma16816(acc[1][3], a1, b1 + 2);
        }
    }

#pragma unroll
    for (int mt = 0; mt < 2; mt++) {
        int m1 = m0 + wm + mt * 16 + g;
        int m2 = m1 + 8;
        int b1 = m1 >> 9, s1 = m1 & 511;
        int b2 = m2 >> 9, s2 = m2 & 511;
#pragma unroll
        for (int nt = 0; nt < 4; nt++) {
            int n = n0 + wn + nt * 8 + 2 * t;
            float2 bv = *(const float2*)&bias[n];
            size_t o1 = ((size_t)s1 * NG + n) * BB + b1;
            size_t o2 = ((size_t)s2 * NG + n) * BB + b2;
            g_gxT[o1]      = acc[mt][nt][0] + bv.x;
            g_gxT[o1 + BB] = acc[mt][nt][1] + bv.y;
            g_gxT[o2]      = acc[mt][nt][2] + bv.x;
            g_gxT[o2 + BB] = acc[mt][nt][3] + bv.y;
        }
    }
}

// ---------------------------------------------------------------------------
// Persistent recurrent kernel: cp.async-pipelined h staging (8 sub-chunks,
// 3 buffers). smem words: Wsh 16512 | Wsl 16512 | 3 x 4352 H | part 8448.
#define LW_SL   16512
#define LHB     33024
#define LHBSZ   4352      // per buffer: Hh 32x68 + Hl 32x68
#define LPART   46080
#define LS_SMEM_BYTES (54528 * 4)

__global__ __launch_bounds__(256, 1) void lstm_layer(
    const float* __restrict__ W, int ldw, int Din,
    float* __restrict__ out, int layer, int rbase)
{
    extern __shared__ uint32_t smu[];
    uint32_t* Wsh = smu;
    uint32_t* Wsl = smu + LW_SL;
    float*    part = (float*)(smu + LPART);
    const uint32_t smb = smaddr(smu);

    const int tid  = threadIdx.x;
    const int j0   = blockIdx.x * 8;
    const int wid  = tid >> 5, lane = tid & 31;
    const int g    = lane >> 2, t4 = lane & 3;

    // ---- Load + split recurrent W slice once (32 rows x 1024 k) ----
    for (int i = 0; i < 64; i++) {
        int q  = i * 256 + tid;
        int l  = q >> 9;
        int wk = q & 511;
        int gate = l >> 3, jj = l & 7;
        int n = gate * 1024 + j0 + jj;
        float2 v = *(const float2*)(W + (size_t)n * ldw + Din + wk * 2);
        __nv_bfloat16 hx = __float2bfloat16(v.x);
        __nv_bfloat16 hy = __float2bfloat16(v.y);
        __nv_bfloat16 lx = __float2bfloat16(v.x - __bfloat162float(hx));
        __nv_bfloat16 ly = __float2bfloat16(v.y - __bfloat162float(hy));
        Wsh[l * 516 + wk] = (uint32_t)__bfloat16_as_ushort(hx)
                          | ((uint32_t)__bfloat16_as_ushort(hy) << 16);
        Wsl[l * 516 + wk] = (uint32_t)__bfloat16_as_ushort(lx)
                          | ((uint32_t)__bfloat16_as_ushort(ly) << 16);
    }

    // update-role mapping: uj fast => contiguous h stores
    const int uj = tid & 7;
    const int ub = tid >> 3;
    const int ujglob = j0 + uj;

    float c_state = 0.0f;
    float h_last  = 0.0f;

    __syncthreads();

    for (int tstep = 0; tstep < SS; tstep++) {
        // gxT prefetch (independent of h)
        size_t gbase = ((size_t)tstep * NG + ujglob) * BB + ub;
        float pi = g_gxT[gbase];
        float pf = g_gxT[gbase + (size_t)1024 * BB];
        float pg = g_gxT[gbase + (size_t)2048 * BB];
        float po = g_gxT[gbase + (size_t)3072 * BB];

        // ---- grid barrier ----
        unsigned round = (unsigned)(rbase + tstep + 1);
        __threadfence();
        __syncthreads();
        if (tid == 0) {
            unsigned arrived = atomicAdd(&g_barCnt, 1u) + 1u;
            if (arrived == round * NCTA) {
                atomicExch(&g_barRel, round);
            } else {
                volatile unsigned* rel = &g_barRel;
                while (*rel < round) {}
            }
            __threadfence();
        }
        __syncthreads();

        if (tstep > 0) {
            float acc[2][4][4];
#pragma unroll
            for (int mt = 0; mt < 2; mt++)
#pragma unroll
                for (int nt = 0; nt < 4; nt++)
#pragma unroll
                    for (int i = 0; i < 4; i++) acc[mt][nt][i] = 0.0f;

            // stage sub-chunk sc (128 bf16 of k) into buffer bf
            auto stageH = [&](int sc, int bf) {
#pragma unroll
                for (int i = 0; i < 4; i++) {
                    int q = i * 256 + tid;            // 0..1023
                    int plane = q >> 9;               // 0 hi, 1 lo
                    int r = q & 511;
                    int b = r >> 4, c = r & 15;
                    uint32_t dst = smb +
                        (LHB + bf * LHBSZ + plane * 2176 + b * 68 + c * 4) * 4;
                    const __nv_bfloat16* src = g_Abig
                        + (size_t)(b * 512 + tstep - 1) * 3072
                        + plane * 1024 + sc * 128 + c * 8;
                    CP16(dst, src);
                }
                CPCOMMIT();
            };

            // mma on sub-chunk sc from buffer bf; warp handles kstep = wid
            auto mmaSub = [&](int sc, int bf) {
                uint32_t* Hh = smu + LHB + bf * LHBSZ;
                uint32_t* Hl = Hh + 2176;
                const int aw = wid * 8 + t4;
                const int bw = (sc * 8 + wid) * 8 + t4;
                uint32_t ah[2][4], al[2][4];
#pragma unroll
                for (int mt = 0; mt < 2; mt++) {
                    int r = mt * 16 + g;
                    ah[mt][0] = Hh[r * 68 + aw];
                    ah[mt][1] = Hh[(r + 8) * 68 + aw];
                    ah[mt][2] = Hh[r * 68 + aw + 4];
                    ah[mt][3] = Hh[(r + 8) * 68 + aw + 4];
                    al[mt][0] = Hl[r * 68 + aw];
                    al[mt][1] = Hl[(r + 8) * 68 + aw];
                    al[mt][2] = Hl[r * 68 + aw + 4];
                    al[mt][3] = Hl[(r + 8) * 68 + aw + 4];
                }
#pragma unroll
                for (int nt = 0; nt < 4; nt++) {
                    int rn = nt * 8 + g;
                    uint32_t bh[2], bl[2];
                    bh[0] = Wsh[rn * 516 + bw];
                    bh[1] = Wsh[rn * 516 + bw + 4];
                    bl[0] = Wsl[rn * 516 + bw];
                    bl[1] = Wsl[rn * 516 + bw + 4];
#pragma unroll
                    for (int mt = 0; mt < 2; mt++) {
                        mma16816(acc[mt][nt], ah[mt], bh);
                        mma16816(acc[mt][nt], ah[mt], bl);
                        mma16816(acc[mt][nt], al[mt], bh);
                    }
                }
            };

            stageH(0, 0);
            stageH(1, 1);
#define LSTEP(sc, pend) \
            cpwaitc<pend>(); __syncthreads(); \
            if ((sc) + 2 < 8) stageH((sc) + 2, ((sc) + 2) % 3); \
            mmaSub(sc, (sc) % 3);
            LSTEP(0, 1) LSTEP(1, 1) LSTEP(2, 1) LSTEP(3, 1)
            LSTEP(4, 1) LSTEP(5, 1) LSTEP(6, 1) LSTEP(7, 0)
#undef LSTEP

            // partials -> smem (scalar: stride 33 is odd)
#pragma unroll
            for (int mt = 0; mt < 2; mt++) {
                int b = mt * 16 + g;
#pragma unroll
                for (int nt = 0; nt < 4; nt++) {
                    int l = nt * 8 + 2 * t4;
                    part[(wid * 32 + b) * 33 + l]     = acc[mt][nt][0];
                    part[(wid * 32 + b) * 33 + l + 1] = acc[mt][nt][1];
                    part[(wid * 32 + b + 8) * 33 + l]     = acc[mt][nt][2];
                    part[(wid * 32 + b + 8) * 33 + l + 1] = acc[mt][nt][3];
                }
            }
            __syncthreads();

#pragma unroll
            for (int w = 0; w < 8; w++) {
                int base = (w * 32 + ub) * 33 + uj;
                pi += part[base];
                pf += part[base + 8];
                pg += part[base + 16];
                po += part[base + 24];
            }
        }

        // ---- activations + state update + h store ----
        float gi = 1.0f / (1.0f + expf(-pi));
        float gf = 1.0f / (1.0f + expf(-pf));
        float gg = tanhf(pg);
        float go = 1.0f / (1.0f + expf(-po));
        c_state = gf * c_state + gi * gg;
        float h = go * tanhf(c_state);
        h_last = h;
        __nv_bfloat16 hh = __float2bfloat16(h);
        __nv_bfloat16 hl = __float2bfloat16(h - __bfloat162float(hh));
        size_t row = (size_t)(ub * 512 + tstep) * 3072;
        g_Abig[row + ujglob]        = hh;
        g_Abig[row + 1024 + ujglob] = hl;
        g_Abig[row + 2048 + ujglob] = hh;
    }

    out[32768 + layer * 32768 + ub * 1024 + ujglob] = h_last;
    out[98304 + layer * 32768 + ub * 1024 + ujglob] = c_state;
    if (layer == 1) out[ub * 1024 + ujglob] = h_last;
}

// ---------------------------------------------------------------------------
extern "C" void kernel_launch(void* const* d_in, const int* in_sizes, int n_in,
                              void* d_out, int out_size)
{
    const float* x  = (const float*)d_in[0];
    const float* W0 = (const float*)d_in[1];
    const float* b0 = (const float*)d_in[2];
    const float* W1 = (const float*)d_in[3];
    const float* b1 = (const float*)d_in[4];
    float* out = (float*)d_out;

    cudaFuncSetAttribute(lstm_layer,
        cudaFuncAttributeMaxDynamicSharedMemorySize, LS_SMEM_BYTES);
    cudaFuncSetAttribute(gemm_x_bf16,
        cudaFuncAttributeMaxDynamicSharedMemorySize, GX_SMEM_BYTES);

    __nv_bfloat16 *Abig, *B0big, *B1big;
    cudaGetSymbolAddress((void**)&Abig,  g_Abig);
    cudaGetSymbolAddress((void**)&B0big, g_B0big);
    cudaGetSymbolAddress((void**)&B1big, g_B1big);

    // Order puts lstm_layer(L0) at my-index 3 (profiled slot w/ harness offset).
    split_x<<<(16384 * 512 + 255) / 256, 256>>>(x);                       // 0
    split_w<<<(4096 * 512 + 255) / 256, 256>>>(W0, INF + HH, 512, B0big, 1536); // 1
    gemm_x_bf16<<<dim3(64, 128), 256, GX_SMEM_BYTES>>>(
        Abig, 3072, B0big, 1536, b0, 1536);                               // 2
    lstm_layer<<<NCTA, 256, LS_SMEM_BYTES>>>(W0, INF + HH, INF, out, 0, 0); // 3
    split_w<<<(4096 * 1024 + 255) / 256, 256>>>(W1, HH + HH, 1024, B1big, 3072); // 4
    gemm_x_bf16<<<dim3(64, 128), 256, GX_SMEM_BYTES>>>(
        Abig, 3072, B1big, 3072, b1, 3072);                               // 5
    lstm_layer<<<NCTA, 256, LS_SMEM_BYTES>>>(W1, HH + HH, HH, out, 1, 512); // 6
}